// round 1
// baseline (speedup 1.0000x reference)
#include <cuda_runtime.h>

// RNN car-following model, GB300 sm_103a.
// One warp per vehicle; the 256-step recurrence runs inside the warp (vehicles
// are independent -> no global sync). Lane = output channel.
//
// Per step: conv1(3ch->32, k=3, SAME, w=25) + relu + maxpool2(SAME, ->13)
//           conv2(32->64, k=3, VALID, ->11) + relu + maxpool2(SAME, ->6)
//           dense 384->10 relu, 10->1, acc = 10*x - 6
//           pos/speed Euler update, sliding window via circular smem buffer.

#define PAST 25
#define WARPS_PER_BLOCK 4
#define THREADS (WARPS_PER_BLOCK * 32)

// shared layout (floats):
//   w1s 288 | b1s 32 | w2s 6144 [ci][k][co] | b2s 64 | d2ws 384*12 | d2bs 16 | d1ws 16
//   per-warp: xs 96 | pool1t 32*17=544 | pool2s 384 | posb 32 | spdb 32  (=1088)
#define WEIGHT_FLOATS (288 + 32 + 6144 + 64 + 384*12 + 16 + 16)
#define WARP_FLOATS   (96 + 544 + 384 + 32 + 32)
#define SMEM_FLOATS   (WEIGHT_FLOATS + WARPS_PER_BLOCK * WARP_FLOATS)
#define SMEM_BYTES    (SMEM_FLOATS * 4)

__global__ __launch_bounds__(THREADS)
void rnncf_kernel(const float* __restrict__ lead,   // [nveh][lead_len][2]
                  const float* __restrict__ curst,  // [nveh][25][2]
                  const float* __restrict__ w1,     // [3][3][32]
                  const float* __restrict__ b1,     // [32]
                  const float* __restrict__ w2,     // [3][32][64]
                  const float* __restrict__ b2,     // [64]
                  const float* __restrict__ d2w,    // [384][10]
                  const float* __restrict__ d2b,    // [10]
                  const float* __restrict__ d1w,    // [10][1]
                  const float* __restrict__ d1b,    // [1]
                  float* __restrict__ out,          // [nveh][nt][2]
                  int nveh, int nt, int lead_len)
{
    extern __shared__ float sm[];
    float* w1s  = sm;              // 288
    float* b1s  = w1s + 288;       // 32
    float* w2s  = b1s + 32;        // 6144, layout [ci][k][co]
    float* b2s  = w2s + 6144;      // 64
    float* d2ws = b2s + 64;        // 384*12 (row padded 10->12, 16B aligned)
    float* d2bs = d2ws + 384*12;   // 16
    float* d1ws = d2bs + 16;       // 16 (w[0..9], bias at [15])
    float* wbase = d1ws + 16;

    const int tid = threadIdx.x;

    // ---- stage weights into shared ----
    for (int i = tid; i < 288; i += THREADS) w1s[i] = w1[i];
    for (int i = tid; i < 32;  i += THREADS) b1s[i] = b1[i];
    for (int i = tid; i < 6144; i += THREADS) {
        int co = i & 63; int r = i >> 6; int ci = r / 3; int k = r - ci * 3;
        w2s[i] = w2[(k * 32 + ci) * 64 + co];   // [k][ci][co] -> [ci][k][co]
    }
    for (int i = tid; i < 64; i += THREADS) b2s[i] = b2[i];
    for (int i = tid; i < 384 * 12; i += THREADS) {
        int o = i % 12; int r = i / 12;
        d2ws[i] = (o < 10) ? d2w[r * 10 + o] : 0.0f;
    }
    if (tid < 10) d2bs[tid] = d2b[tid];
    if (tid < 10) d1ws[tid] = d1w[tid];
    if (tid == 0) d1ws[15] = d1b[0];
    __syncthreads();

    const int warp = tid >> 5;
    const int lane = tid & 31;
    const int v = blockIdx.x * WARPS_PER_BLOCK + warp;
    if (v >= nveh) return;

    float* xs     = wbase + warp * WARP_FLOATS;   // [3][32] channel-major
    float* pool1t = xs + 96;                      // [ci][17] (13 used, pad 17: odd -> conflict-free)
    float* pool2s = pool1t + 544;                 // [6][64] == flatten order
    float* posb   = pool2s + 384;                 // circular 32
    float* spdb   = posb + 32;                    // circular 32

    const float* leadv = lead + (size_t)v * lead_len * 2;

    if (lane < PAST) {
        posb[lane] = curst[(v * PAST + lane) * 2 + 0];
        spdb[lane] = curst[(v * PAST + lane) * 2 + 1];
    }

    // conv1 weights register-resident: w1r[k*3+ci] = w1[k][ci][lane]
    float w1r[9];
#pragma unroll
    for (int q = 0; q < 9; q++) w1r[q] = w1s[q * 32 + lane];
    const float b1r  = b1s[lane];
    const float b2r0 = b2s[lane];
    const float b2r1 = b2s[lane + 32];
    const float d1bias = d1ws[15];

    int head = 0;
    __syncwarp();

    for (int t = 0; t < nt; t++) {
        // ---- A: build input window x[25][3] (channel-major in smem) ----
        if (lane < PAST) {
            int s = t + lane;
            float lp  = leadv[2 * s];
            float lsv = leadv[2 * s + 1];
            float pw = posb[(head + lane) & 31];
            float sw = spdb[(head + lane) & 31];
            xs[lane]      = (lp - pw) * (1.0f / 200.0f);  // /MAXHD
            xs[32 + lane] = sw  * (1.0f / 40.0f);         // /MAXV
            xs[64 + lane] = lsv * (1.0f / 40.0f);         // /MAXV
        }
        __syncwarp();

        // ---- B: conv1 (SAME) + relu + maxpool2 -> pool1t[ci][13] ----
        {
            float xm0 = 0.f, xm1 = 0.f, xm2 = 0.f;          // col w-1
            float x00 = xs[0], x01 = xs[32], x02 = xs[64];  // col w
            float prev = 0.f;
#pragma unroll
            for (int w = 0; w < 25; w++) {
                float xp0, xp1, xp2;                        // col w+1
                if (w < 24) { xp0 = xs[w + 1]; xp1 = xs[32 + w + 1]; xp2 = xs[64 + w + 1]; }
                else        { xp0 = 0.f; xp1 = 0.f; xp2 = 0.f; }
                float val = b1r;
                val = fmaf(xm0, w1r[0], val); val = fmaf(xm1, w1r[1], val); val = fmaf(xm2, w1r[2], val);
                val = fmaf(x00, w1r[3], val); val = fmaf(x01, w1r[4], val); val = fmaf(x02, w1r[5], val);
                val = fmaf(xp0, w1r[6], val); val = fmaf(xp1, w1r[7], val); val = fmaf(xp2, w1r[8], val);
                val = fmaxf(val, 0.0f);
                if ((w & 1) == 0) {
                    if (w == 24) pool1t[lane * 17 + 12] = val;   // last pool window has 1 elem (SAME)
                    else prev = val;
                } else {
                    pool1t[lane * 17 + (w >> 1)] = fmaxf(prev, val);
                }
                xm0 = x00; xm1 = x01; xm2 = x02;
                x00 = xp0; x01 = xp1; x02 = xp2;
            }
        }
        __syncwarp();

        // ---- C: conv2 (VALID, 32->64) : lane handles co=lane and co=lane+32 ----
        float a0[11], a1[11];
#pragma unroll
        for (int q = 0; q < 11; q++) { a0[q] = 0.f; a1[q] = 0.f; }
#pragma unroll 4
        for (int ci = 0; ci < 32; ci++) {
            float p[13];
#pragma unroll
            for (int j = 0; j < 13; j++) p[j] = pool1t[ci * 17 + j];   // broadcast
            float wa0 = w2s[(ci * 3 + 0) * 64 + lane];
            float wa1 = w2s[(ci * 3 + 1) * 64 + lane];
            float wa2 = w2s[(ci * 3 + 2) * 64 + lane];
            float wb0 = w2s[(ci * 3 + 0) * 64 + lane + 32];
            float wb1 = w2s[(ci * 3 + 1) * 64 + lane + 32];
            float wb2 = w2s[(ci * 3 + 2) * 64 + lane + 32];
#pragma unroll
            for (int q = 0; q < 11; q++) {
                a0[q] = fmaf(p[q],     wa0, a0[q]);
                a0[q] = fmaf(p[q + 1], wa1, a0[q]);
                a0[q] = fmaf(p[q + 2], wa2, a0[q]);
                a1[q] = fmaf(p[q],     wb0, a1[q]);
                a1[q] = fmaf(p[q + 1], wb1, a1[q]);
                a1[q] = fmaf(p[q + 2], wb2, a1[q]);
            }
        }
        // bias + relu + maxpool2 (SAME: pairs (0,1)..(8,9),(10,pad)) -> pool2s[6][64]
#pragma unroll
        for (int pp = 0; pp < 6; pp++) {
            float r0 = fmaxf(a0[2 * pp] + b2r0, 0.0f);
            float r1 = fmaxf(a1[2 * pp] + b2r1, 0.0f);
            if (pp < 5) {
                r0 = fmaxf(r0, fmaxf(a0[2 * pp + 1] + b2r0, 0.0f));
                r1 = fmaxf(r1, fmaxf(a1[2 * pp + 1] + b2r1, 0.0f));
            }
            pool2s[pp * 64 + lane]      = r0;
            pool2s[pp * 64 + lane + 32] = r1;
        }
        __syncwarp();

        // ---- D: dense 384->10 (lane-partial + butterfly), relu, dense 10->1 ----
        float h[10];
#pragma unroll
        for (int o = 0; o < 10; o++) h[o] = 0.f;
#pragma unroll
        for (int m = 0; m < 12; m++) {
            int i = m * 32 + lane;
            float xv = pool2s[i];
            const float4* wp = (const float4*)&d2ws[i * 12];
            float4 wA = wp[0];
            float4 wB = wp[1];
            float2 wC = *(const float2*)&d2ws[i * 12 + 8];
            h[0] = fmaf(xv, wA.x, h[0]); h[1] = fmaf(xv, wA.y, h[1]);
            h[2] = fmaf(xv, wA.z, h[2]); h[3] = fmaf(xv, wA.w, h[3]);
            h[4] = fmaf(xv, wB.x, h[4]); h[5] = fmaf(xv, wB.y, h[5]);
            h[6] = fmaf(xv, wB.z, h[6]); h[7] = fmaf(xv, wB.w, h[7]);
            h[8] = fmaf(xv, wC.x, h[8]); h[9] = fmaf(xv, wC.y, h[9]);
        }
#pragma unroll
        for (int off = 16; off > 0; off >>= 1) {
#pragma unroll
            for (int o = 0; o < 10; o++)
                h[o] += __shfl_xor_sync(0xffffffffu, h[o], off);
        }
        float s = d1bias;
#pragma unroll
        for (int o = 0; o < 10; o++)
            s = fmaf(fmaxf(h[o] + d2bs[o], 0.0f), d1ws[o], s);
        float accv = 10.0f * s - 6.0f;   // (MAXA-MINA)*x + MINA

        // ---- E: state update + output ----
        if (lane == 0) {
            float p24 = posb[(head + 24) & 31];
            float s24 = spdb[(head + 24) & 31];
            float np = p24 + 0.1f * s24;
            float ns = s24 + 0.1f * accv;
            size_t ob = ((size_t)v * nt + t) * 2;
            out[ob]     = np;
            out[ob + 1] = ns;
            posb[(head + 25) & 31] = np;
            spdb[(head + 25) & 31] = ns;
        }
        head = (head + 1) & 31;
        __syncwarp();
    }
}

extern "C" void kernel_launch(void* const* d_in, const int* in_sizes, int n_in,
                              void* d_out, int out_size) {
    const float* lead = (const float*)d_in[0];
    const float* curs = (const float*)d_in[1];
    // d_in[2] = mask : unused by the reference
    const float* w1  = (const float*)d_in[3];
    const float* b1  = (const float*)d_in[4];
    const float* w2  = (const float*)d_in[5];
    const float* b2  = (const float*)d_in[6];
    const float* d2w = (const float*)d_in[7];
    const float* d2b = (const float*)d_in[8];
    const float* d1w = (const float*)d_in[9];
    const float* d1b = (const float*)d_in[10];

    int nveh = in_sizes[1] / (2 * PAST);
    int lead_len = in_sizes[0] / (nveh * 2);
    int nt = out_size / (nveh * 2);

    cudaFuncSetAttribute(rnncf_kernel, cudaFuncAttributeMaxDynamicSharedMemorySize, SMEM_BYTES);

    int blocks = (nveh + WARPS_PER_BLOCK - 1) / WARPS_PER_BLOCK;
    rnncf_kernel<<<blocks, THREADS, SMEM_BYTES>>>(
        lead, curs, w1, b1, w2, b2, d2w, d2b, d1w, d1b,
        (float*)d_out, nveh, nt, lead_len);
}